// round 9
// baseline (speedup 1.0000x reference)
#include <cuda_runtime.h>
#include <cstdint>

#define NB     64
#define NCAND  22743      // 3*(19^2 + 38^2 + 76^2)
#define NCPAD  22744      // padded: per-image key rows 16B-aligned
#define MCAND  256
#define NEGF   (-1e9f)
#define FULLW  0xffffffffu

__constant__ float c_anchors[3][3][2] = {
  {{116.f, 90.f},{156.f,198.f},{373.f,326.f}},
  {{ 30.f, 61.f},{ 62.f, 45.f},{ 59.f,119.f}},
  {{ 10.f, 13.f},{ 16.f, 30.f},{ 33.f, 23.f}}
};

__device__ __align__(16) uint32_t g_keys[(size_t)NB * NCPAD];

__device__ __forceinline__ uint32_t fkey(float f) {
  uint32_t u = __float_as_uint(f);
  return (u & 0x80000000u) ? ~u : (u | 0x80000000u);
}

struct Cand { float x1, y1, x2, y2, val; int cls; };

// math shared by both decode paths; f[26] = raw record
__device__ __forceinline__ Cand decode_math(const float* f, int lvl, int a,
                                            int gi, int gj, float stride)
{
  float sx  = 1.f / (1.f + expf(-f[0]));
  float sy  = 1.f / (1.f + expf(-f[1]));
  float obj = 1.f / (1.f + expf(-f[4]));
  float loc = 1.f / (1.f + expf(-f[5]));
  float cx = (sx + (float)gj) * stride;
  float cy = (sy + (float)gi) * stride;
  float w = expf(f[2]) * c_anchors[lvl][a][0];
  float h = expf(f[3]) * c_anchors[lvl][a][1];

  float maxl = -1e30f; int ci = 0;
  #pragma unroll
  for (int k = 0; k < 20; k++)
    if (f[6+k] > maxl) { maxl = f[6+k]; ci = k; }
  float sum = 0.f;
  #pragma unroll
  for (int k = 0; k < 20; k++) sum += expf(f[6+k] - maxl);
  float conf = 1.0f / sum;

  float x1 = fminf(fmaxf(cx - 0.5f * w, 0.f), 608.f);
  float y1 = fminf(fmaxf(cy - 0.5f * h, 0.f), 608.f);
  float x2 = fminf(fmaxf(cx + 0.5f * w, 0.f), 608.f);
  float y2 = fminf(fmaxf(cy + 0.5f * h, 0.f), 608.f);

  bool valid = (obj >= 0.6f) && (obj * conf >= 0.05f) && (loc >= 0.5f);
  float score = sqrtf(obj * conf) * sqrtf(loc);

  Cand c;
  c.x1 = x1; c.y1 = y1; c.x2 = x2; c.y2 = y2;
  c.val = valid ? score : NEGF;
  c.cls = ci;
  return c;
}

__device__ __forceinline__ void level_of(int n, const float* l0, const float* l1,
                                         const float* l2, const float*& base,
                                         int& G, int& lvl, int& m, float& stride)
{
  if (n < 1083)      { base = l0; G = 19; stride = 32.f; lvl = 0; m = n;        }
  else if (n < 5415) { base = l1; G = 38; stride = 16.f; lvl = 1; m = n - 1083; }
  else               { base = l2; G = 76; stride =  8.f; lvl = 2; m = n - 5415; }
}

__device__ __forceinline__ Cand decode_cand(
    int b, int n,
    const float* __restrict__ l0, const float* __restrict__ l1,
    const float* __restrict__ l2)
{
  const float* base; int G, lvl, m; float stride;
  level_of(n, l0, l1, l2, base, G, lvl, m, stride);
  int GG = G * G;
  int a  = m / GG;
  int r  = m - a * GG;
  int gi = r / G;
  int gj = r - gi * G;
  const float2* __restrict__ p2 =
      reinterpret_cast<const float2*>(base + ((size_t)(b * 3 + a) * GG + r) * 26);
  float f[26];
  #pragma unroll
  for (int i = 0; i < 13; i++) { float2 v = p2[i]; f[2*i] = v.x; f[2*i+1] = v.y; }
  return decode_math(f, lvl, a, gi, gj, stride);
}

// -------- Kernel A: decode every anchor; warp-coalesced record staging --------
__global__ void decode_score_kernel(const float* __restrict__ l0,
                                    const float* __restrict__ l1,
                                    const float* __restrict__ l2)
{
  __shared__ float stage[8][832];        // 8 warps x 32 records x 26 f32 = 26.6 KB
  int idx = blockIdx.x * 256 + threadIdx.x;
  int wrp = threadIdx.x >> 5, lane = threadIdx.x & 31;
  int b = idx / NCPAD;
  int n = idx - b * NCPAD;

  const float* base; int G, lvl, m; float stride;
  // pad lanes get a harmless level classification (n>=NCAND handled below)
  level_of(n < NCAND ? n : 0, l0, l1, l2, base, G, lvl, m, stride);
  if (n >= NCAND) lvl = -1;

  int b0   = __shfl_sync(FULLW, b, 0);
  int b31  = __shfl_sync(FULLW, b, 31);
  int l0w  = __shfl_sync(FULLW, lvl, 0);
  int l31w = __shfl_sync(FULLW, lvl, 31);
  bool uniform = (b0 == b31) && (l0w == l31w) && (l31w >= 0);

  float f[26];
  int GG = G * G;
  int a  = m / GG;
  int r  = m - a * GG;
  int gi = r / G;
  int gj = r - gi * G;

  if (uniform) {
    // 32 contiguous records = 3328 B; coalesced float2 loads -> smem -> own record
    int m0 = m - lane;
    const float2* __restrict__ src =
        reinterpret_cast<const float2*>(base + ((size_t)b * 3 * GG + m0) * 26);
    float2* dst = reinterpret_cast<float2*>(stage[wrp]);
    #pragma unroll
    for (int k = 0; k < 13; k++) dst[lane + 32 * k] = src[lane + 32 * k];
    __syncwarp();
    const float2* rec = reinterpret_cast<const float2*>(stage[wrp] + lane * 26);
    #pragma unroll
    for (int i = 0; i < 13; i++) { float2 v = rec[i]; f[2*i] = v.x; f[2*i+1] = v.y; }
    __syncwarp();
  } else {
    if (n >= NCAND) { g_keys[idx] = 0u; return; }   // pad key, never selected
    const float2* __restrict__ p2 =
        reinterpret_cast<const float2*>(base + ((size_t)(b * 3 + a) * GG + r) * 26);
    #pragma unroll
    for (int i = 0; i < 13; i++) { float2 v = p2[i]; f[2*i] = v.x; f[2*i+1] = v.y; }
  }

  Cand c = decode_math(f, lvl, a, gi, gj, stride);
  g_keys[idx] = fkey(c.val);
}

// -------- Kernel B+D merged: radix-select top-256 + soft-NMS + top-8 ---------
__global__ void select_nms_kernel(const float* __restrict__ l0,
                                  const float* __restrict__ l1,
                                  const float* __restrict__ l2,
                                  float* __restrict__ out)
{
  int b = blockIdx.x;
  int t = threadIdx.x;
  int lane = t & 31;

  extern __shared__ uint32_t smem_sel[];
  uint32_t* skeys = smem_sel;                 // NCPAD
  int* hist = (int*)(smem_sel + NCPAD);       // 256
  int* suf  = hist + 256;                     // 256
  __shared__ int sel[MCAND];
  __shared__ int s_rem, s_abv, s_d;
  __shared__ int c_gt, c_eq;

  // ---- stage keys once (vectorized) ----
  {
    const uint4* __restrict__ gk4 = (const uint4*)(g_keys + (size_t)b * NCPAD);
    uint4* sk4 = (uint4*)skeys;
    for (int i = t; i < NCPAD / 4; i += 1024) sk4[i] = gk4[i];
  }
  if (t == 0) { c_gt = 0; c_eq = 0; }
  __syncthreads();

  // ---- 4-pass radix select with warp-aggregated histogram atomics ----
  uint32_t prefix = 0, mask = 0;
  int remaining = MCAND, above = 0;

  #pragma unroll
  for (int pass = 0; pass < 4; pass++) {
    int shift = 24 - pass * 8;
    if (t < 256) hist[t] = 0;
    __syncthreads();
    for (int nb = 0; nb < NCPAD; nb += 1024) {   // uniform trip count
      int n = nb + t;
      bool in = n < NCPAD;
      uint32_t k = in ? skeys[n] : 0u;
      bool active = in && ((k & mask) == prefix);
      unsigned am = __ballot_sync(FULLW, active);
      if (active) {
        int bin = (k >> shift) & 0xFF;
        unsigned peers = __match_any_sync(am, bin);
        if ((peers & ((1u << lane) - 1)) == 0)          // leader of this bin
          atomicAdd(&hist[bin], __popc(peers));
      }
    }
    __syncthreads();
    if (t < 256) suf[t] = hist[t];
    __syncthreads();
    for (int off = 1; off < 256; off <<= 1) {
      int v = (t < 256 && t + off < 256) ? suf[t + off] : 0;
      __syncthreads();
      if (t < 256) suf[t] += v;
      __syncthreads();
    }
    if (t < 256) {
      int sd  = suf[t];
      int sd1 = (t == 255) ? 0 : suf[t + 1];
      if (sd >= remaining && sd1 < remaining) {
        s_d = t; s_rem = remaining - sd1; s_abv = above + sd1;
      }
    }
    __syncthreads();
    prefix |= ((uint32_t)s_d) << shift;
    remaining = s_rem;
    above     = s_abv;
    mask |= (0xFFu << shift);
    __syncthreads();
  }

  uint32_t T = prefix;            // exact key of the 256th-largest
  int cnt_gt = above;             // strictly-greater count (< 256)
  int need_eq = MCAND - cnt_gt;

  // ---- compaction, warp-aggregated (robust even when T is mass-duplicated) ----
  for (int nb = 0; nb < NCPAD; nb += 1024) {
    int n = nb + t;
    bool in = n < NCAND;          // pad excluded
    uint32_t k = in ? skeys[n] : 0u;
    bool gt = in && (k > T);
    bool eq = in && (k == T);
    unsigned mgt = __ballot_sync(FULLW, gt);
    unsigned meq = __ballot_sync(FULLW, eq);
    if (gt) {
      int rank = __popc(mgt & ((1u << lane) - 1));
      int bpos = 0;
      int ldr = __ffs(mgt) - 1;
      if (lane == ldr) bpos = atomicAdd(&c_gt, __popc(mgt));
      bpos = __shfl_sync(mgt, bpos, ldr);
      sel[bpos + rank] = n;
    }
    if (eq) {
      int rank = __popc(meq & ((1u << lane) - 1));
      int bpos = 0;
      int ldr = __ffs(meq) - 1;
      if (lane == ldr) bpos = atomicAdd(&c_eq, __popc(meq));
      bpos = __shfl_sync(meq, bpos, ldr);
      if (bpos + rank < need_eq) sel[cnt_gt + bpos + rank] = n;
    }
  }
  __syncthreads();

  // ================= NMS phase =================
  __shared__ float sx1[MCAND], sy1[MCAND], sx2[MCAND], sy2[MCAND];
  __shared__ float ss[MCAND], sval[MCAND];
  __shared__ int   scls[MCAND];
  __shared__ unsigned char skept[MCAND];
  __shared__ int ccount[20], cbase[20], cfill[20];
  __shared__ short order[MCAND];

  if (t < 20) { ccount[t] = 0; cfill[t] = 0; }
  __syncthreads();

  int mycls = -1;
  if (t < MCAND) {
    Cand c = decode_cand(b, sel[t], l0, l1, l2);
    sx1[t] = c.x1; sy1[t] = c.y1; sx2[t] = c.x2; sy2[t] = c.y2;
    sval[t] = c.val;
    ss[t]   = c.val;
    scls[t] = c.cls;
    skept[t] = 0;
    mycls = c.cls;
    atomicAdd(&ccount[mycls], 1);
  }
  __syncthreads();
  if (t == 0) {
    int acc = 0;
    #pragma unroll
    for (int k = 0; k < 20; k++) { cbase[k] = acc; acc += ccount[k]; }
  }
  __syncthreads();
  if (t < MCAND) {
    int slot = atomicAdd(&cfill[mycls], 1);
    order[cbase[mycls] + slot] = (short)t;
  }
  __syncthreads();

  // class-decomposed soft-NMS: one warp per class
  int w = t >> 5;
  if (w < 20) {
    int nc = ccount[w];
    int base2 = cbase[w];
    const uint32_t thresh = fkey(0.1f);   // NMS_T
    while (true) {
      unsigned long long best = 0ull;
      for (int mm = lane; mm < nc; mm += 32) {
        int i = order[base2 + mm];
        unsigned long long pk =
            (((unsigned long long)fkey(ss[i])) << 32) | (unsigned)(255 - i);
        if (pk > best) best = pk;
      }
      #pragma unroll
      for (int off = 16; off; off >>= 1) {
        unsigned long long o = __shfl_xor_sync(FULLW, best, off);
        if (o > best) best = o;
      }
      if ((uint32_t)(best >> 32) < thresh) break;
      int bi = 255 - (int)(best & 0xffffffffu);

      float bx1 = sx1[bi], by1 = sy1[bi], bx2 = sx2[bi], by2 = sy2[bi];
      float a1 = (bx2 - bx1 + 1.f) * (by2 - by1 + 1.f);
      __syncwarp();
      for (int mm = lane; mm < nc; mm += 32) {
        int i = order[base2 + mm];
        float ix1 = fmaxf(bx1, sx1[i]);
        float iy1 = fmaxf(by1, sy1[i]);
        float ix2 = fminf(bx2, sx2[i]);
        float iy2 = fminf(by2, sy2[i]);
        float inter = fmaxf(ix2 - ix1 + 1.f, 0.f) * fmaxf(iy2 - iy1 + 1.f, 0.f);
        float a2 = (sx2[i] - sx1[i] + 1.f) * (sy2[i] - sy1[i] + 1.f);
        float iou = inter / (a1 + a2 - inter + 1e-16f);
        ss[i] *= expf(-2.0f * iou * iou);   // exp(-iou^2 / sigma), sigma=0.5
      }
      __syncwarp();
      if (lane == 0) { skept[bi] = 1; ss[bi] = NEGF; }
      __syncwarp();
    }
  }
  __syncthreads();

  // top-8 among kept by ORIGINAL score (lowest-index tiebreak) — warp 0 only
  if (t < 32) {
    float v[8];
    #pragma unroll
    for (int k = 0; k < 8; k++) {
      int j = (k << 5) | t;
      v[k] = skept[j] ? sval[j] : NEGF;
    }
    const uint32_t okkey = fkey(-5e8f);     // NEG/2 cutoff
    for (int r = 0; r < 8; r++) {
      unsigned long long best = 0ull;
      #pragma unroll
      for (int k = 0; k < 8; k++) {
        int j = (k << 5) | t;
        unsigned long long pk =
            (((unsigned long long)fkey(v[k])) << 32) | (unsigned)(255 - j);
        if (pk > best) best = pk;
      }
      #pragma unroll
      for (int off = 16; off; off >>= 1) {
        unsigned long long o = __shfl_xor_sync(FULLW, best, off);
        if (o > best) best = o;
      }
      int jw = 255 - (int)(best & 0xffffffffu);
      uint32_t kw = (uint32_t)(best >> 32);
      if ((jw & 31) == t) {
        float* o = out + ((size_t)b * 8 + r) * 6;
        if (kw > okkey) {
          o[0] = sx1[jw]; o[1] = sy1[jw]; o[2] = sx2[jw]; o[3] = sy2[jw];
          o[4] = sval[jw]; o[5] = (float)scls[jw];
        } else {
          o[0] = 0.f; o[1] = 0.f; o[2] = 0.f; o[3] = 0.f; o[4] = 0.f; o[5] = 0.f;
        }
        v[jw >> 5] = NEGF;
      }
    }
  }
}

extern "C" void kernel_launch(void* const* d_in, const int* in_sizes, int n_in,
                              void* d_out, int out_size)
{
  const float* l0 = nullptr; const float* l1 = nullptr; const float* l2 = nullptr;
  for (int i = 0; i < n_in; i++) {
    if      (in_sizes[i] == 64 * 3 * 19 * 19 * 26) l0 = (const float*)d_in[i];
    else if (in_sizes[i] == 64 * 3 * 38 * 38 * 26) l1 = (const float*)d_in[i];
    else if (in_sizes[i] == 64 * 3 * 76 * 76 * 26) l2 = (const float*)d_in[i];
  }
  float* out = (float*)d_out;

  size_t sel_smem = (size_t)(NCPAD + 512) * sizeof(uint32_t);
  static bool attr_done = false;
  if (!attr_done) {
    cudaFuncSetAttribute(select_nms_kernel,
                         cudaFuncAttributeMaxDynamicSharedMemorySize,
                         (int)sel_smem);
    attr_done = true;
  }

  int total = NB * NCPAD;                   // 1,455,616 = 5686 * 256
  decode_score_kernel<<<total / 256, 256>>>(l0, l1, l2);
  select_nms_kernel<<<NB, 1024, sel_smem>>>(l0, l1, l2, out);
}